// round 1
// baseline (speedup 1.0000x reference)
#include <cuda_runtime.h>
#include <math.h>

#define D        512
#define BMAX     16
#define NCHUNK   32
#define NEG_INF  -1e30f

// ---------------- scratch (no allocation allowed) ----------------
__device__ float g_q[BMAX * D];                    // q = query @ W_align^T + b_align
__device__ float g_pm[BMAX * NCHUNK];              // per-chunk running max
__device__ float g_ps[BMAX * NCHUNK];              // per-chunk denom (rel. to g_pm)
__device__ float g_pctx[BMAX * NCHUNK * D];        // per-chunk partial context

// ---------------- K1: q = query @ W_align^T + b_align ----------------
// grid = B, block = 256 (8 warps). Warp computes outputs d = warp, warp+8, ...
__global__ void __launch_bounds__(256) k1_qproj(
    const float* __restrict__ query,
    const float* __restrict__ W_align,
    const float* __restrict__ b_align)
{
    const int b = blockIdx.x;
    __shared__ float qs[D];
    for (int i = threadIdx.x; i < D; i += blockDim.x) qs[i] = query[b * D + i];
    __syncthreads();

    const int warp = threadIdx.x >> 5;
    const int lane = threadIdx.x & 31;
    const float4* q4 = reinterpret_cast<const float4*>(qs);

    float4 x[4];
#pragma unroll
    for (int k = 0; k < 4; k++) x[k] = q4[lane + 32 * k];

    for (int d = warp; d < D; d += 8) {
        const float4* wrow = reinterpret_cast<const float4*>(W_align + (size_t)d * D);
        float acc = 0.f;
#pragma unroll
        for (int k = 0; k < 4; k++) {
            float4 w = wrow[lane + 32 * k];
            acc += w.x * x[k].x + w.y * x[k].y + w.z * x[k].z + w.w * x[k].w;
        }
#pragma unroll
        for (int o = 16; o > 0; o >>= 1) acc += __shfl_xor_sync(0xffffffffu, acc, o);
        if (lane == 0) g_q[b * D + d] = acc + b_align[d];
    }
}

// ---------------- K2: single-pass online-softmax over value ----------------
// grid = B*NCHUNK, block = 256 (8 warps). Warp-per-row, lane covers 16 d-cols.
__global__ void __launch_bounds__(256) k2_attn(
    const float* __restrict__ value,
    const int*   __restrict__ mask,
    int L)
{
    const int b   = blockIdx.x / NCHUNK;
    const int c   = blockIdx.x % NCHUNK;
    const int RC  = L / NCHUNK;           // rows per chunk
    const int l0  = c * RC;
    const int warp = threadIdx.x >> 5;
    const int lane = threadIdx.x & 31;

    // q[b] into registers, float4-strided so value loads are coalesced
    const float4* q4 = reinterpret_cast<const float4*>(g_q + b * D);
    float4 q[4];
#pragma unroll
    for (int k = 0; k < 4; k++) q[k] = q4[lane + 32 * k];

    float m = NEG_INF, s = 0.f;
    float4 ctx[4];
#pragma unroll
    for (int k = 0; k < 4; k++) ctx[k] = make_float4(0.f, 0.f, 0.f, 0.f);

    for (int l = l0 + warp; l < l0 + RC; l += 8) {
        const float4* vrow =
            reinterpret_cast<const float4*>(value + ((size_t)b * L + l) * D);
        float4 v[4];
#pragma unroll
        for (int k = 0; k < 4; k++) v[k] = vrow[lane + 32 * k];

        float p = 0.f;
#pragma unroll
        for (int k = 0; k < 4; k++)
            p += v[k].x * q[k].x + v[k].y * q[k].y + v[k].z * q[k].z + v[k].w * q[k].w;
#pragma unroll
        for (int o = 16; o > 0; o >>= 1) p += __shfl_xor_sync(0xffffffffu, p, o);

        if (mask[(size_t)b * L + l] != 0) p = NEG_INF;

        const float m_new = fmaxf(m, p);
        const float corr  = __expf(m - m_new);   // 1 when m==m_new
        const float w     = __expf(p - m_new);   // 0 when masked & m_new finite
        s = s * corr + w;
#pragma unroll
        for (int k = 0; k < 4; k++) {
            ctx[k].x = fmaf(ctx[k].x, corr, w * v[k].x);
            ctx[k].y = fmaf(ctx[k].y, corr, w * v[k].y);
            ctx[k].z = fmaf(ctx[k].z, corr, w * v[k].z);
            ctx[k].w = fmaf(ctx[k].w, corr, w * v[k].w);
        }
        m = m_new;
    }

    // merge the 8 warps' partials
    __shared__ float sm_m[8], sm_s[8];
    __shared__ float sm_ctx[8][D];
    if (lane == 0) { sm_m[warp] = m; sm_s[warp] = s; }
#pragma unroll
    for (int k = 0; k < 4; k++) {
        const int i = (lane + 32 * k) * 4;
        sm_ctx[warp][i + 0] = ctx[k].x;
        sm_ctx[warp][i + 1] = ctx[k].y;
        sm_ctx[warp][i + 2] = ctx[k].z;
        sm_ctx[warp][i + 3] = ctx[k].w;
    }
    __syncthreads();

    float M = NEG_INF;
#pragma unroll
    for (int wi = 0; wi < 8; wi++) M = fmaxf(M, sm_m[wi]);

    float e[8];
#pragma unroll
    for (int wi = 0; wi < 8; wi++) e[wi] = __expf(sm_m[wi] - M);

    float o0 = 0.f, o1 = 0.f;
#pragma unroll
    for (int wi = 0; wi < 8; wi++) {
        o0 += sm_ctx[wi][threadIdx.x]       * e[wi];
        o1 += sm_ctx[wi][threadIdx.x + 256] * e[wi];
    }
    const int pidx = b * NCHUNK + c;
    g_pctx[(size_t)pidx * D + threadIdx.x]       = o0;
    g_pctx[(size_t)pidx * D + threadIdx.x + 256] = o1;

    if (threadIdx.x == 0) {
        float S = 0.f;
#pragma unroll
        for (int wi = 0; wi < 8; wi++) S += sm_s[wi] * e[wi];
        g_pm[pidx] = M;
        g_ps[pidx] = S;
    }
}

// ---------------- K3: combine chunks + out = tanh(ctx@Wv^T + bv + q@Wq^T + bq) ----------------
// grid = B, block = 256 (8 warps)
__global__ void __launch_bounds__(256) k3_out(
    const float* __restrict__ W_query,
    const float* __restrict__ b_query,
    const float* __restrict__ W_value,
    const float* __restrict__ b_value,
    float* __restrict__ out)
{
    const int b = blockIdx.x;
    __shared__ float e_sm[NCHUNK];
    __shared__ float ctxs[D];
    __shared__ float qs[D];
    __shared__ float Sinv_sm;

    // global max / rescale factors over chunks
    float M = NEG_INF;
#pragma unroll
    for (int c = 0; c < NCHUNK; c++) M = fmaxf(M, g_pm[b * NCHUNK + c]);
    if (threadIdx.x < NCHUNK)
        e_sm[threadIdx.x] = __expf(g_pm[b * NCHUNK + threadIdx.x] - M);
    __syncthreads();

    if (threadIdx.x == 0) {
        float S = 0.f;
#pragma unroll
        for (int c = 0; c < NCHUNK; c++) S += g_ps[b * NCHUNK + c] * e_sm[c];
        Sinv_sm = 1.f / S;
    }
    __syncthreads();
    const float Sinv = Sinv_sm;

    // combined, normalized context
#pragma unroll
    for (int r = 0; r < 2; r++) {
        const int d = threadIdx.x + 256 * r;
        float acc = 0.f;
#pragma unroll
        for (int c = 0; c < NCHUNK; c++)
            acc += g_pctx[((size_t)b * NCHUNK + c) * D + d] * e_sm[c];
        ctxs[d] = acc * Sinv;
    }
    for (int i = threadIdx.x; i < D; i += blockDim.x) qs[i] = g_q[b * D + i];
    __syncthreads();

    const int warp = threadIdx.x >> 5;
    const int lane = threadIdx.x & 31;
    const float4* c4 = reinterpret_cast<const float4*>(ctxs);
    const float4* q4 = reinterpret_cast<const float4*>(qs);

    float4 cx[4], qx[4];
#pragma unroll
    for (int k = 0; k < 4; k++) { cx[k] = c4[lane + 32 * k]; qx[k] = q4[lane + 32 * k]; }

    for (int d = warp; d < D; d += 8) {
        const float4* wv = reinterpret_cast<const float4*>(W_value + (size_t)d * D);
        const float4* wq = reinterpret_cast<const float4*>(W_query + (size_t)d * D);
        float acc = 0.f;
#pragma unroll
        for (int k = 0; k < 4; k++) {
            float4 a = wv[lane + 32 * k];
            float4 bq4 = wq[lane + 32 * k];
            acc += a.x * cx[k].x + a.y * cx[k].y + a.z * cx[k].z + a.w * cx[k].w;
            acc += bq4.x * qx[k].x + bq4.y * qx[k].y + bq4.z * qx[k].z + bq4.w * qx[k].w;
        }
#pragma unroll
        for (int o = 16; o > 0; o >>= 1) acc += __shfl_xor_sync(0xffffffffu, acc, o);
        if (lane == 0)
            out[b * D + d] = tanhf(acc + b_value[d] + b_query[d]);
    }
}

// ---------------- launch ----------------
extern "C" void kernel_launch(void* const* d_in, const int* in_sizes, int n_in,
                              void* d_out, int out_size)
{
    const float* query   = (const float*)d_in[0];
    const float* value   = (const float*)d_in[1];
    const int*   mask    = (const int*)  d_in[2];
    const float* W_align = (const float*)d_in[3];
    const float* b_align = (const float*)d_in[4];
    const float* W_query = (const float*)d_in[5];
    const float* b_query = (const float*)d_in[6];
    const float* W_value = (const float*)d_in[7];
    const float* b_value = (const float*)d_in[8];
    float* out = (float*)d_out;

    const int B = in_sizes[0] / D;          // 16
    const int L = in_sizes[2] / B;          // 8192

    k1_qproj<<<B, 256>>>(query, W_align, b_align);
    k2_attn <<<B * NCHUNK, 256>>>(value, mask, L);
    k3_out  <<<B, 256>>>(W_query, b_query, W_value, b_value, out);
}

// round 2
// speedup vs baseline: 3.8503x; 3.8503x over previous
#include <cuda_runtime.h>
#include <math.h>

#define D        512
#define BMAX     16
#define NCHUNK   32
#define NEG_INF  -1e30f

// ---------------- scratch (no allocation allowed) ----------------
__device__ float g_q[BMAX * D];                    // q = query @ W_align^T + b_align
__device__ float g_pm[BMAX * NCHUNK];              // per-chunk running max
__device__ float g_ps[BMAX * NCHUNK];              // per-chunk denom (rel. to g_pm)
__device__ float g_pctx[BMAX * NCHUNK * D];        // per-chunk partial context

// ---------------- K1: q = query @ W_align^T + b_align ----------------
// grid = (B, 8), block = 256 (8 warps). Each block computes 64 outputs;
// each warp computes outputs d = seg*64 + warp + 8*i, i<8.
__global__ void __launch_bounds__(256) k1_qproj(
    const float* __restrict__ query,
    const float* __restrict__ W_align,
    const float* __restrict__ b_align)
{
    const int b   = blockIdx.x;
    const int seg = blockIdx.y;
    __shared__ float qs[D];
    for (int i = threadIdx.x; i < D; i += blockDim.x) qs[i] = query[b * D + i];
    __syncthreads();

    const int warp = threadIdx.x >> 5;
    const int lane = threadIdx.x & 31;
    const float4* q4 = reinterpret_cast<const float4*>(qs);

    float4 x[4];
#pragma unroll
    for (int k = 0; k < 4; k++) x[k] = q4[lane + 32 * k];

#pragma unroll
    for (int i = 0; i < 8; i++) {
        const int d = seg * 64 + i * 8 + warp;
        const float4* wrow = reinterpret_cast<const float4*>(W_align + (size_t)d * D);
        float acc = 0.f;
#pragma unroll
        for (int k = 0; k < 4; k++) {
            float4 w = wrow[lane + 32 * k];
            acc = fmaf(w.x, x[k].x, acc); acc = fmaf(w.y, x[k].y, acc);
            acc = fmaf(w.z, x[k].z, acc); acc = fmaf(w.w, x[k].w, acc);
        }
#pragma unroll
        for (int o = 16; o > 0; o >>= 1) acc += __shfl_xor_sync(0xffffffffu, acc, o);
        if (lane == 0) g_q[b * D + d] = acc + b_align[d];
    }
}

// ---------------- K2: single-pass online-softmax over value ----------------
// grid = B*NCHUNK, block = 256 (8 warps). Each warp owns 32 contiguous rows,
// ballots the mask, and only loads UNMASKED value rows (2 per iteration).
__global__ void __launch_bounds__(256) k2_attn(
    const float* __restrict__ value,
    const int*   __restrict__ mask,
    int L)
{
    const int b    = blockIdx.x / NCHUNK;
    const int c    = blockIdx.x % NCHUNK;
    const int RC   = L / NCHUNK;           // rows per chunk (256)
    const int l0   = c * RC;
    const int warp = threadIdx.x >> 5;
    const int lane = threadIdx.x & 31;

    // q[b] into registers, float4-strided so value loads are coalesced
    const float4* q4 = reinterpret_cast<const float4*>(g_q + b * D);
    float4 q[4];
#pragma unroll
    for (int k = 0; k < 4; k++) q[k] = q4[lane + 32 * k];

    float m = NEG_INF, s = 0.f;
    float4 ctx[4];
#pragma unroll
    for (int k = 0; k < 4; k++) ctx[k] = make_float4(0.f, 0.f, 0.f, 0.f);

    const int ROWS_PER_WARP = RC / 8;       // 32
    const int lw0 = l0 + warp * ROWS_PER_WARP;

    // one coalesced mask load covers this warp's 32 rows
    unsigned act = __ballot_sync(0xffffffffu,
                                 mask[(size_t)b * L + lw0 + lane] == 0);

    while (act) {
        const int i1 = __ffs(act) - 1; act &= act - 1;
        int i2 = -1;
        if (act) { i2 = __ffs(act) - 1; act &= act - 1; }

        const float4* v1p = reinterpret_cast<const float4*>(
            value + ((size_t)b * L + lw0 + i1) * D);
        const float4* v2p = reinterpret_cast<const float4*>(
            value + ((size_t)b * L + lw0 + ((i2 >= 0) ? i2 : i1)) * D);

        float4 v1[4], v2[4];
#pragma unroll
        for (int k = 0; k < 4; k++) v1[k] = __ldcs(v1p + lane + 32 * k);
#pragma unroll
        for (int k = 0; k < 4; k++) v2[k] = __ldcs(v2p + lane + 32 * k);

        float p1 = 0.f, p2 = 0.f;
#pragma unroll
        for (int k = 0; k < 4; k++) {
            p1 = fmaf(v1[k].x, q[k].x, p1); p1 = fmaf(v1[k].y, q[k].y, p1);
            p1 = fmaf(v1[k].z, q[k].z, p1); p1 = fmaf(v1[k].w, q[k].w, p1);
            p2 = fmaf(v2[k].x, q[k].x, p2); p2 = fmaf(v2[k].y, q[k].y, p2);
            p2 = fmaf(v2[k].z, q[k].z, p2); p2 = fmaf(v2[k].w, q[k].w, p2);
        }
#pragma unroll
        for (int o = 16; o > 0; o >>= 1) {
            p1 += __shfl_xor_sync(0xffffffffu, p1, o);
            p2 += __shfl_xor_sync(0xffffffffu, p2, o);
        }
        if (i2 < 0) p2 = NEG_INF;

        const float m_new = fmaxf(m, fmaxf(p1, p2));
        const float corr  = __expf(m  - m_new);
        const float w1    = __expf(p1 - m_new);
        const float w2    = __expf(p2 - m_new);
        s = s * corr + w1 + w2;
#pragma unroll
        for (int k = 0; k < 4; k++) {
            ctx[k].x = fmaf(ctx[k].x, corr, fmaf(w1, v1[k].x, w2 * v2[k].x));
            ctx[k].y = fmaf(ctx[k].y, corr, fmaf(w1, v1[k].y, w2 * v2[k].y));
            ctx[k].z = fmaf(ctx[k].z, corr, fmaf(w1, v1[k].z, w2 * v2[k].z));
            ctx[k].w = fmaf(ctx[k].w, corr, fmaf(w1, v1[k].w, w2 * v2[k].w));
        }
        m = m_new;
    }

    // merge the 8 warps' partials
    __shared__ float sm_m[8], sm_s[8];
    __shared__ float sm_ctx[8][D];
    if (lane == 0) { sm_m[warp] = m; sm_s[warp] = s; }
#pragma unroll
    for (int k = 0; k < 4; k++) {
        const int i = (lane + 32 * k) * 4;
        sm_ctx[warp][i + 0] = ctx[k].x;
        sm_ctx[warp][i + 1] = ctx[k].y;
        sm_ctx[warp][i + 2] = ctx[k].z;
        sm_ctx[warp][i + 3] = ctx[k].w;
    }
    __syncthreads();

    float M = NEG_INF;
#pragma unroll
    for (int wi = 0; wi < 8; wi++) M = fmaxf(M, sm_m[wi]);

    float e[8];
#pragma unroll
    for (int wi = 0; wi < 8; wi++) e[wi] = __expf(sm_m[wi] - M);

    float o0 = 0.f, o1 = 0.f;
#pragma unroll
    for (int wi = 0; wi < 8; wi++) {
        o0 = fmaf(sm_ctx[wi][threadIdx.x],       e[wi], o0);
        o1 = fmaf(sm_ctx[wi][threadIdx.x + 256], e[wi], o1);
    }
    const int pidx = b * NCHUNK + c;
    g_pctx[(size_t)pidx * D + threadIdx.x]       = o0;
    g_pctx[(size_t)pidx * D + threadIdx.x + 256] = o1;

    if (threadIdx.x == 0) {
        float S = 0.f;
#pragma unroll
        for (int wi = 0; wi < 8; wi++) S = fmaf(sm_s[wi], e[wi], S);
        g_pm[pidx] = M;
        g_ps[pidx] = S;
    }
}

// ---------------- K3: combine chunks + out = tanh(ctx@Wv^T + bv + q@Wq^T + bq) ----------------
// grid = (B, 8), block = 256 (8 warps). Each block redundantly combines the
// chunk partials (L2-resident, cheap), then computes 64 outputs.
__global__ void __launch_bounds__(256) k3_out(
    const float* __restrict__ W_query,
    const float* __restrict__ b_query,
    const float* __restrict__ W_value,
    const float* __restrict__ b_value,
    float* __restrict__ out)
{
    const int b   = blockIdx.x;
    const int seg = blockIdx.y;
    __shared__ float e_sm[NCHUNK];
    __shared__ float ctxs[D];
    __shared__ float qs[D];
    __shared__ float Sinv_sm;

    float M = NEG_INF;
#pragma unroll
    for (int c = 0; c < NCHUNK; c++) M = fmaxf(M, g_pm[b * NCHUNK + c]);
    if (threadIdx.x < NCHUNK)
        e_sm[threadIdx.x] = __expf(g_pm[b * NCHUNK + threadIdx.x] - M);
    __syncthreads();

    if (threadIdx.x == 0) {
        float S = 0.f;
#pragma unroll
        for (int c = 0; c < NCHUNK; c++) S = fmaf(g_ps[b * NCHUNK + c], e_sm[c], S);
        Sinv_sm = 1.f / S;
    }
    __syncthreads();
    const float Sinv = Sinv_sm;

#pragma unroll
    for (int r = 0; r < 2; r++) {
        const int d = threadIdx.x + 256 * r;
        float acc = 0.f;
#pragma unroll
        for (int c = 0; c < NCHUNK; c++)
            acc = fmaf(g_pctx[((size_t)b * NCHUNK + c) * D + d], e_sm[c], acc);
        ctxs[d] = acc * Sinv;
    }
    for (int i = threadIdx.x; i < D; i += blockDim.x) qs[i] = g_q[b * D + i];
    __syncthreads();

    const int warp = threadIdx.x >> 5;
    const int lane = threadIdx.x & 31;
    const float4* c4 = reinterpret_cast<const float4*>(ctxs);
    const float4* q4 = reinterpret_cast<const float4*>(qs);

    float4 cx[4], qx[4];
#pragma unroll
    for (int k = 0; k < 4; k++) { cx[k] = c4[lane + 32 * k]; qx[k] = q4[lane + 32 * k]; }

#pragma unroll
    for (int i = 0; i < 8; i++) {
        const int d = seg * 64 + i * 8 + warp;
        const float4* wv = reinterpret_cast<const float4*>(W_value + (size_t)d * D);
        const float4* wq = reinterpret_cast<const float4*>(W_query + (size_t)d * D);
        float acc = 0.f;
#pragma unroll
        for (int k = 0; k < 4; k++) {
            float4 a  = wv[lane + 32 * k];
            float4 g  = wq[lane + 32 * k];
            acc = fmaf(a.x, cx[k].x, acc); acc = fmaf(a.y, cx[k].y, acc);
            acc = fmaf(a.z, cx[k].z, acc); acc = fmaf(a.w, cx[k].w, acc);
            acc = fmaf(g.x, qx[k].x, acc); acc = fmaf(g.y, qx[k].y, acc);
            acc = fmaf(g.z, qx[k].z, acc); acc = fmaf(g.w, qx[k].w, acc);
        }
#pragma unroll
        for (int o = 16; o > 0; o >>= 1) acc += __shfl_xor_sync(0xffffffffu, acc, o);
        if (lane == 0)
            out[b * D + d] = tanhf(acc + b_value[d] + b_query[d]);
    }
}

// ---------------- launch ----------------
extern "C" void kernel_launch(void* const* d_in, const int* in_sizes, int n_in,
                              void* d_out, int out_size)
{
    const float* query   = (const float*)d_in[0];
    const float* value   = (const float*)d_in[1];
    const int*   mask    = (const int*)  d_in[2];
    const float* W_align = (const float*)d_in[3];
    const float* b_align = (const float*)d_in[4];
    const float* W_query = (const float*)d_in[5];
    const float* b_query = (const float*)d_in[6];
    const float* W_value = (const float*)d_in[7];
    const float* b_value = (const float*)d_in[8];
    float* out = (float*)d_out;

    const int B = in_sizes[0] / D;          // 16
    const int L = in_sizes[2] / B;          // 8192

    k1_qproj<<<dim3(B, 8), 256>>>(query, W_align, b_align);
    k2_attn <<<B * NCHUNK, 256>>>(value, mask, L);
    k3_out  <<<dim3(B, 8), 256>>>(W_query, b_query, W_value, b_value, out);
}

// round 3
// speedup vs baseline: 5.1201x; 1.3298x over previous
#include <cuda_runtime.h>
#include <math.h>

#define D        512
#define BMAX     16
#define NCHUNK   32
#define NEG_INF  -1e30f

// ---------------- scratch (no allocation allowed) ----------------
__device__ float g_q[BMAX * D];                    // q = query @ W_align^T + b_align
__device__ float g_pm[BMAX * NCHUNK];              // per-chunk running max
__device__ float g_ps[BMAX * NCHUNK];              // per-chunk denom (rel. to g_pm)
__device__ float g_pctx[BMAX * NCHUNK * D];        // per-chunk partial context

// ---------------- K1: q = query @ W_align^T + b_align ----------------
// grid = (B, 64), block = 256 (8 warps). Warp w computes output d = seg*8 + w.
// 8192 independent warps -> latency fully hidden.
__global__ void __launch_bounds__(256) k1_qproj(
    const float* __restrict__ query,
    const float* __restrict__ W_align,
    const float* __restrict__ b_align)
{
    const int b    = blockIdx.x;
    const int warp = threadIdx.x >> 5;
    const int lane = threadIdx.x & 31;
    const int d    = blockIdx.y * 8 + warp;

    const float4* q4   = reinterpret_cast<const float4*>(query + (size_t)b * D);
    const float4* wrow = reinterpret_cast<const float4*>(W_align + (size_t)d * D);

    float acc = 0.f;
#pragma unroll
    for (int k = 0; k < 4; k++) {
        float4 x = q4[lane + 32 * k];
        float4 w = wrow[lane + 32 * k];
        acc = fmaf(w.x, x.x, acc); acc = fmaf(w.y, x.y, acc);
        acc = fmaf(w.z, x.z, acc); acc = fmaf(w.w, x.w, acc);
    }
#pragma unroll
    for (int o = 16; o > 0; o >>= 1) acc += __shfl_xor_sync(0xffffffffu, acc, o);
    if (lane == 0) g_q[b * D + d] = acc + b_align[d];
}

// ---------------- K2: single-pass online-softmax over value ----------------
// grid = B*NCHUNK, block = 256 (8 warps). Each warp owns 32 contiguous rows,
// ballots the mask, loads only UNMASKED rows, 4 per iteration (MLP=16/thread).
__global__ void __launch_bounds__(256) k2_attn(
    const float* __restrict__ value,
    const int*   __restrict__ mask,
    int L)
{
    const int b    = blockIdx.x / NCHUNK;
    const int c    = blockIdx.x % NCHUNK;
    const int RC   = L / NCHUNK;           // rows per chunk (256)
    const int l0   = c * RC;
    const int warp = threadIdx.x >> 5;
    const int lane = threadIdx.x & 31;

    const float4* q4 = reinterpret_cast<const float4*>(g_q + b * D);
    float4 q[4];
#pragma unroll
    for (int k = 0; k < 4; k++) q[k] = q4[lane + 32 * k];

    float m = NEG_INF, s = 0.f;
    float4 ctx[4];
#pragma unroll
    for (int k = 0; k < 4; k++) ctx[k] = make_float4(0.f, 0.f, 0.f, 0.f);

    const int ROWS_PER_WARP = RC / 8;       // 32
    const int lw0 = l0 + warp * ROWS_PER_WARP;
    const float* vbase = value + ((size_t)b * L + lw0) * D;

    // one coalesced mask load covers this warp's 32 rows
    unsigned act = __ballot_sync(0xffffffffu,
                                 mask[(size_t)b * L + lw0 + lane] == 0);

    while (act) {
        int j0 = __ffs(act) - 1; act &= act - 1;
        int n = 1, j1 = j0, j2 = j0, j3 = j0;
        if (act) { j1 = __ffs(act) - 1; act &= act - 1; n = 2;
            if (act) { j2 = __ffs(act) - 1; act &= act - 1; n = 3;
                if (act) { j3 = __ffs(act) - 1; act &= act - 1; n = 4; } } }

        const float4* p0 = reinterpret_cast<const float4*>(vbase + (size_t)j0 * D);
        const float4* p1 = reinterpret_cast<const float4*>(vbase + (size_t)j1 * D);
        const float4* p2 = reinterpret_cast<const float4*>(vbase + (size_t)j2 * D);
        const float4* p3 = reinterpret_cast<const float4*>(vbase + (size_t)j3 * D);

        float4 v0[4], v1[4], v2[4], v3[4];
#pragma unroll
        for (int k = 0; k < 4; k++) v0[k] = __ldcs(p0 + lane + 32 * k);
#pragma unroll
        for (int k = 0; k < 4; k++) v1[k] = __ldcs(p1 + lane + 32 * k);
#pragma unroll
        for (int k = 0; k < 4; k++) v2[k] = __ldcs(p2 + lane + 32 * k);
#pragma unroll
        for (int k = 0; k < 4; k++) v3[k] = __ldcs(p3 + lane + 32 * k);

        float s0 = 0.f, s1 = 0.f, s2 = 0.f, s3 = 0.f;
#pragma unroll
        for (int k = 0; k < 4; k++) {
            s0 = fmaf(v0[k].x, q[k].x, s0); s0 = fmaf(v0[k].y, q[k].y, s0);
            s0 = fmaf(v0[k].z, q[k].z, s0); s0 = fmaf(v0[k].w, q[k].w, s0);
            s1 = fmaf(v1[k].x, q[k].x, s1); s1 = fmaf(v1[k].y, q[k].y, s1);
            s1 = fmaf(v1[k].z, q[k].z, s1); s1 = fmaf(v1[k].w, q[k].w, s1);
            s2 = fmaf(v2[k].x, q[k].x, s2); s2 = fmaf(v2[k].y, q[k].y, s2);
            s2 = fmaf(v2[k].z, q[k].z, s2); s2 = fmaf(v2[k].w, q[k].w, s2);
            s3 = fmaf(v3[k].x, q[k].x, s3); s3 = fmaf(v3[k].y, q[k].y, s3);
            s3 = fmaf(v3[k].z, q[k].z, s3); s3 = fmaf(v3[k].w, q[k].w, s3);
        }
#pragma unroll
        for (int o = 16; o > 0; o >>= 1) {
            s0 += __shfl_xor_sync(0xffffffffu, s0, o);
            s1 += __shfl_xor_sync(0xffffffffu, s1, o);
            s2 += __shfl_xor_sync(0xffffffffu, s2, o);
            s3 += __shfl_xor_sync(0xffffffffu, s3, o);
        }
        if (n < 2) s1 = NEG_INF;
        if (n < 3) s2 = NEG_INF;
        if (n < 4) s3 = NEG_INF;

        const float m_new = fmaxf(fmaxf(m, fmaxf(s0, s1)), fmaxf(s2, s3));
        const float corr = __expf(m  - m_new);
        const float w0   = __expf(s0 - m_new);
        const float w1   = __expf(s1 - m_new);
        const float w2   = __expf(s2 - m_new);
        const float w3   = __expf(s3 - m_new);
        s = s * corr + w0 + w1 + w2 + w3;
#pragma unroll
        for (int k = 0; k < 4; k++) {
            ctx[k].x = fmaf(fmaf(w1, v1[k].x, w0 * v0[k].x) + fmaf(w3, v3[k].x, w2 * v2[k].x),
                            1.f, ctx[k].x * corr);
            ctx[k].y = fmaf(fmaf(w1, v1[k].y, w0 * v0[k].y) + fmaf(w3, v3[k].y, w2 * v2[k].y),
                            1.f, ctx[k].y * corr);
            ctx[k].z = fmaf(fmaf(w1, v1[k].z, w0 * v0[k].z) + fmaf(w3, v3[k].z, w2 * v2[k].z),
                            1.f, ctx[k].z * corr);
            ctx[k].w = fmaf(fmaf(w1, v1[k].w, w0 * v0[k].w) + fmaf(w3, v3[k].w, w2 * v2[k].w),
                            1.f, ctx[k].w * corr);
        }
        m = m_new;
    }

    // merge the 8 warps' partials
    __shared__ float sm_m[8], sm_s[8];
    __shared__ float sm_ctx[8][D];
    if (lane == 0) { sm_m[warp] = m; sm_s[warp] = s; }
#pragma unroll
    for (int k = 0; k < 4; k++) {
        const int i = (lane + 32 * k) * 4;
        sm_ctx[warp][i + 0] = ctx[k].x;
        sm_ctx[warp][i + 1] = ctx[k].y;
        sm_ctx[warp][i + 2] = ctx[k].z;
        sm_ctx[warp][i + 3] = ctx[k].w;
    }
    __syncthreads();

    float M = NEG_INF;
#pragma unroll
    for (int wi = 0; wi < 8; wi++) M = fmaxf(M, sm_m[wi]);

    float e[8];
#pragma unroll
    for (int wi = 0; wi < 8; wi++) e[wi] = __expf(sm_m[wi] - M);

    float o0 = 0.f, o1 = 0.f;
#pragma unroll
    for (int wi = 0; wi < 8; wi++) {
        o0 = fmaf(sm_ctx[wi][threadIdx.x],       e[wi], o0);
        o1 = fmaf(sm_ctx[wi][threadIdx.x + 256], e[wi], o1);
    }
    const int pidx = b * NCHUNK + c;
    g_pctx[(size_t)pidx * D + threadIdx.x]       = o0;
    g_pctx[(size_t)pidx * D + threadIdx.x + 256] = o1;

    if (threadIdx.x == 0) {
        float S = 0.f;
#pragma unroll
        for (int wi = 0; wi < 8; wi++) S = fmaf(sm_s[wi], e[wi], S);
        g_pm[pidx] = M;
        g_ps[pidx] = S;
    }
}

// ---------------- K3: combine chunks + out = tanh(ctx@Wv^T + bv + q@Wq^T + bq) ----------------
// grid = (B, 16), block = 256 (8 warps). Each block redundantly combines the
// chunk partials (64KB L2/block), then computes 32 outputs (4 per warp).
__global__ void __launch_bounds__(256) k3_out(
    const float* __restrict__ W_query,
    const float* __restrict__ b_query,
    const float* __restrict__ W_value,
    const float* __restrict__ b_value,
    float* __restrict__ out)
{
    const int b   = blockIdx.x;
    const int seg = blockIdx.y;
    __shared__ float e_sm[NCHUNK];
    __shared__ float ctxs[D];
    __shared__ float qs[D];
    __shared__ float Sinv_sm;

    float M = NEG_INF;
#pragma unroll
    for (int c = 0; c < NCHUNK; c++) M = fmaxf(M, g_pm[b * NCHUNK + c]);
    if (threadIdx.x < NCHUNK)
        e_sm[threadIdx.x] = __expf(g_pm[b * NCHUNK + threadIdx.x] - M);
    __syncthreads();

    if (threadIdx.x == 0) {
        float S = 0.f;
#pragma unroll
        for (int c = 0; c < NCHUNK; c++) S = fmaf(g_ps[b * NCHUNK + c], e_sm[c], S);
        Sinv_sm = 1.f / S;
    }
    __syncthreads();
    const float Sinv = Sinv_sm;

#pragma unroll
    for (int r = 0; r < 2; r++) {
        const int d = threadIdx.x + 256 * r;
        float acc = 0.f;
#pragma unroll
        for (int c = 0; c < NCHUNK; c++)
            acc = fmaf(g_pctx[((size_t)b * NCHUNK + c) * D + d], e_sm[c], acc);
        ctxs[d] = acc * Sinv;
    }
    for (int i = threadIdx.x; i < D; i += blockDim.x) qs[i] = g_q[b * D + i];
    __syncthreads();

    const int warp = threadIdx.x >> 5;
    const int lane = threadIdx.x & 31;
    const float4* c4 = reinterpret_cast<const float4*>(ctxs);
    const float4* q4 = reinterpret_cast<const float4*>(qs);

    float4 cx[4], qx[4];
#pragma unroll
    for (int k = 0; k < 4; k++) { cx[k] = c4[lane + 32 * k]; qx[k] = q4[lane + 32 * k]; }

#pragma unroll
    for (int i = 0; i < 4; i++) {
        const int d = seg * 32 + i * 8 + warp;
        const float4* wv = reinterpret_cast<const float4*>(W_value + (size_t)d * D);
        const float4* wq = reinterpret_cast<const float4*>(W_query + (size_t)d * D);
        float acc = 0.f;
#pragma unroll
        for (int k = 0; k < 4; k++) {
            float4 a = wv[lane + 32 * k];
            float4 g = wq[lane + 32 * k];
            acc = fmaf(a.x, cx[k].x, acc); acc = fmaf(a.y, cx[k].y, acc);
            acc = fmaf(a.z, cx[k].z, acc); acc = fmaf(a.w, cx[k].w, acc);
            acc = fmaf(g.x, qx[k].x, acc); acc = fmaf(g.y, qx[k].y, acc);
            acc = fmaf(g.z, qx[k].z, acc); acc = fmaf(g.w, qx[k].w, acc);
        }
#pragma unroll
        for (int o = 16; o > 0; o >>= 1) acc += __shfl_xor_sync(0xffffffffu, acc, o);
        if (lane == 0)
            out[b * D + d] = tanhf(acc + b_value[d] + b_query[d]);
    }
}

// ---------------- launch ----------------
extern "C" void kernel_launch(void* const* d_in, const int* in_sizes, int n_in,
                              void* d_out, int out_size)
{
    const float* query   = (const float*)d_in[0];
    const float* value   = (const float*)d_in[1];
    const int*   mask    = (const int*)  d_in[2];
    const float* W_align = (const float*)d_in[3];
    const float* b_align = (const float*)d_in[4];
    const float* W_query = (const float*)d_in[5];
    const float* b_query = (const float*)d_in[6];
    const float* W_value = (const float*)d_in[7];
    const float* b_value = (const float*)d_in[8];
    float* out = (float*)d_out;

    const int B = in_sizes[0] / D;          // 16
    const int L = in_sizes[2] / B;          // 8192

    k1_qproj<<<dim3(B, 64), 256>>>(query, W_align, b_align);
    k2_attn <<<B * NCHUNK, 256>>>(value, mask, L);
    k3_out  <<<dim3(B, 16), 256>>>(W_query, b_query, W_value, b_value, out);
}

// round 4
// speedup vs baseline: 5.6395x; 1.1014x over previous
#include <cuda_runtime.h>
#include <math.h>

#define D        512
#define BMAX     16
#define NCHUNK   16
#define NEG_INF  -1e30f

// ---------------- scratch (no allocation allowed) ----------------
__device__ float g_q[BMAX * D];                    // q = query @ W_align^T + b_align
__device__ float g_pm[BMAX * NCHUNK];              // per-chunk running max
__device__ float g_ps[BMAX * NCHUNK];              // per-chunk denom (rel. to g_pm)
__device__ float g_pctx[BMAX * NCHUNK * D];        // per-chunk partial context
__device__ float g_ctx[BMAX * D];                  // combined, normalized context

// ---------------- K1: q = query @ W_align^T + b_align ----------------
// grid = (B, 16), block = 256 (8 warps). Each warp computes 4 consecutive
// outputs -> 20 independent float4 loads in flight per thread.
__global__ void __launch_bounds__(256) k1_qproj(
    const float* __restrict__ query,
    const float* __restrict__ W_align,
    const float* __restrict__ b_align)
{
    const int b    = blockIdx.x;
    const int warp = threadIdx.x >> 5;
    const int lane = threadIdx.x & 31;
    const int d0   = blockIdx.y * 32 + warp * 4;

    const float4* q4 = reinterpret_cast<const float4*>(query + (size_t)b * D);
    float4 x[4];
#pragma unroll
    for (int k = 0; k < 4; k++) x[k] = q4[lane + 32 * k];

    float acc[4] = {0.f, 0.f, 0.f, 0.f};
#pragma unroll
    for (int i = 0; i < 4; i++) {
        const float4* wrow = reinterpret_cast<const float4*>(W_align + (size_t)(d0 + i) * D);
#pragma unroll
        for (int k = 0; k < 4; k++) {
            float4 w = wrow[lane + 32 * k];
            acc[i] = fmaf(w.x, x[k].x, acc[i]); acc[i] = fmaf(w.y, x[k].y, acc[i]);
            acc[i] = fmaf(w.z, x[k].z, acc[i]); acc[i] = fmaf(w.w, x[k].w, acc[i]);
        }
    }
#pragma unroll
    for (int o = 16; o > 0; o >>= 1) {
#pragma unroll
        for (int i = 0; i < 4; i++) acc[i] += __shfl_xor_sync(0xffffffffu, acc[i], o);
    }
    if (lane < 4) g_q[b * D + d0 + lane] = acc[lane] + b_align[d0 + lane];
}

// ---------------- K2: single-pass online-softmax over value ----------------
// grid = B*NCHUNK (256 blocks = one resident wave), block = 256 (8 warps).
// Block compacts the unmasked rows of its 512-row chunk into smem, then warps
// consume them in a statically balanced interleave, 4 rows per iteration.
__global__ void __launch_bounds__(256) k2_attn(
    const float* __restrict__ value,
    const int*   __restrict__ mask,
    int L)
{
    const int b    = blockIdx.x / NCHUNK;
    const int c    = blockIdx.x % NCHUNK;
    const int RC   = L / NCHUNK;           // rows per chunk (512)
    const int l0   = c * RC;
    const int tid  = threadIdx.x;
    const int warp = tid >> 5;
    const int lane = tid & 31;

    __shared__ int   s_idx[512];
    __shared__ int   s_pop[16], s_off[16], s_total;

    // ---- compact unmasked row indices (deterministic) ----
    const int* mrow = mask + (size_t)b * L + l0;
    unsigned a0 = __ballot_sync(0xffffffffu, mrow[tid]       == 0);
    unsigned a1 = __ballot_sync(0xffffffffu, mrow[tid + 256] == 0);
    if (lane == 0) { s_pop[warp] = __popc(a0); s_pop[warp + 8] = __popc(a1); }
    __syncthreads();
    if (tid == 0) {
        int acc = 0;
#pragma unroll
        for (int i = 0; i < 16; i++) { s_off[i] = acc; acc += s_pop[i]; }
        s_total = acc;
    }
    __syncthreads();
    if ((a0 >> lane) & 1)
        s_idx[s_off[warp]     + __popc(a0 & ((1u << lane) - 1))] = warp * 32 + lane;
    if ((a1 >> lane) & 1)
        s_idx[s_off[warp + 8] + __popc(a1 & ((1u << lane) - 1))] = 256 + warp * 32 + lane;
    __syncthreads();
    const int T = s_total;

    // ---- q into registers (float4-strided) ----
    const float4* q4 = reinterpret_cast<const float4*>(g_q + b * D);
    float4 q[4];
#pragma unroll
    for (int k = 0; k < 4; k++) q[k] = q4[lane + 32 * k];

    float m = NEG_INF, s = 0.f;
    float4 ctx[4];
#pragma unroll
    for (int k = 0; k < 4; k++) ctx[k] = make_float4(0.f, 0.f, 0.f, 0.f);

    const float* vbase = value + ((size_t)b * L + l0) * D;

    for (int t0 = warp * 4; t0 < T; t0 += 32) {
        const int n = min(4, T - t0);
        const int j0 = s_idx[t0];
        const int j1 = s_idx[t0 + (n > 1 ? 1 : 0)];
        const int j2 = s_idx[t0 + (n > 2 ? 2 : 0)];
        const int j3 = s_idx[t0 + (n > 3 ? 3 : 0)];

        const float4* p0 = reinterpret_cast<const float4*>(vbase + (size_t)j0 * D);
        const float4* p1 = reinterpret_cast<const float4*>(vbase + (size_t)j1 * D);
        const float4* p2 = reinterpret_cast<const float4*>(vbase + (size_t)j2 * D);
        const float4* p3 = reinterpret_cast<const float4*>(vbase + (size_t)j3 * D);

        float4 v0[4], v1[4], v2[4], v3[4];
#pragma unroll
        for (int k = 0; k < 4; k++) v0[k] = __ldcs(p0 + lane + 32 * k);
#pragma unroll
        for (int k = 0; k < 4; k++) v1[k] = __ldcs(p1 + lane + 32 * k);
#pragma unroll
        for (int k = 0; k < 4; k++) v2[k] = __ldcs(p2 + lane + 32 * k);
#pragma unroll
        for (int k = 0; k < 4; k++) v3[k] = __ldcs(p3 + lane + 32 * k);

        float s0 = 0.f, s1 = 0.f, s2 = 0.f, s3 = 0.f;
#pragma unroll
        for (int k = 0; k < 4; k++) {
            s0 = fmaf(v0[k].x, q[k].x, s0); s0 = fmaf(v0[k].y, q[k].y, s0);
            s0 = fmaf(v0[k].z, q[k].z, s0); s0 = fmaf(v0[k].w, q[k].w, s0);
            s1 = fmaf(v1[k].x, q[k].x, s1); s1 = fmaf(v1[k].y, q[k].y, s1);
            s1 = fmaf(v1[k].z, q[k].z, s1); s1 = fmaf(v1[k].w, q[k].w, s1);
            s2 = fmaf(v2[k].x, q[k].x, s2); s2 = fmaf(v2[k].y, q[k].y, s2);
            s2 = fmaf(v2[k].z, q[k].z, s2); s2 = fmaf(v2[k].w, q[k].w, s2);
            s3 = fmaf(v3[k].x, q[k].x, s3); s3 = fmaf(v3[k].y, q[k].y, s3);
            s3 = fmaf(v3[k].w, q[k].w, s3); s3 = fmaf(v3[k].z, q[k].z, s3);
        }
#pragma unroll
        for (int o = 16; o > 0; o >>= 1) {
            s0 += __shfl_xor_sync(0xffffffffu, s0, o);
            s1 += __shfl_xor_sync(0xffffffffu, s1, o);
            s2 += __shfl_xor_sync(0xffffffffu, s2, o);
            s3 += __shfl_xor_sync(0xffffffffu, s3, o);
        }
        if (n < 2) s1 = NEG_INF;
        if (n < 3) s2 = NEG_INF;
        if (n < 4) s3 = NEG_INF;

        const float m_new = fmaxf(fmaxf(m, fmaxf(s0, s1)), fmaxf(s2, s3));
        const float corr = __expf(m  - m_new);
        const float w0   = __expf(s0 - m_new);
        const float w1   = __expf(s1 - m_new);
        const float w2   = __expf(s2 - m_new);
        const float w3   = __expf(s3 - m_new);
        s = s * corr + w0 + w1 + w2 + w3;
#pragma unroll
        for (int k = 0; k < 4; k++) {
            ctx[k].x = ctx[k].x * corr + fmaf(w1, v1[k].x, w0 * v0[k].x)
                                       + fmaf(w3, v3[k].x, w2 * v2[k].x);
            ctx[k].y = ctx[k].y * corr + fmaf(w1, v1[k].y, w0 * v0[k].y)
                                       + fmaf(w3, v3[k].y, w2 * v2[k].y);
            ctx[k].z = ctx[k].z * corr + fmaf(w1, v1[k].z, w0 * v0[k].z)
                                       + fmaf(w3, v3[k].z, w2 * v2[k].z);
            ctx[k].w = ctx[k].w * corr + fmaf(w1, v1[k].w, w0 * v0[k].w)
                                       + fmaf(w3, v3[k].w, w2 * v2[k].w);
        }
        m = m_new;
    }

    // ---- merge the 8 warps' partials ----
    __shared__ float sm_m[8], sm_s[8];
    __shared__ float sm_ctx[8][D];
    if (lane == 0) { sm_m[warp] = m; sm_s[warp] = s; }
#pragma unroll
    for (int k = 0; k < 4; k++) {
        const int i = (lane + 32 * k) * 4;
        sm_ctx[warp][i + 0] = ctx[k].x;
        sm_ctx[warp][i + 1] = ctx[k].y;
        sm_ctx[warp][i + 2] = ctx[k].z;
        sm_ctx[warp][i + 3] = ctx[k].w;
    }
    __syncthreads();

    float M = NEG_INF;
#pragma unroll
    for (int wi = 0; wi < 8; wi++) M = fmaxf(M, sm_m[wi]);

    float e[8];
#pragma unroll
    for (int wi = 0; wi < 8; wi++) e[wi] = __expf(sm_m[wi] - M);

    float o0 = 0.f, o1 = 0.f;
#pragma unroll
    for (int wi = 0; wi < 8; wi++) {
        o0 = fmaf(sm_ctx[wi][tid],       e[wi], o0);
        o1 = fmaf(sm_ctx[wi][tid + 256], e[wi], o1);
    }
    const int pidx = b * NCHUNK + c;
    g_pctx[(size_t)pidx * D + tid]       = o0;
    g_pctx[(size_t)pidx * D + tid + 256] = o1;

    if (tid == 0) {
        float S = 0.f;
#pragma unroll
        for (int wi = 0; wi < 8; wi++) S = fmaf(sm_s[wi], e[wi], S);
        g_pm[pidx] = M;
        g_ps[pidx] = S;
    }
}

// ---------------- K3a: combine chunk partials -> g_ctx (normalized) ----------------
// grid = B, block = 256. Each thread combines 2 d-columns across 16 chunks.
__global__ void __launch_bounds__(256) k3a_combine()
{
    const int b   = blockIdx.x;
    const int tid = threadIdx.x;
    __shared__ float e_sm[NCHUNK];
    __shared__ float Sinv_sm;

    float M = NEG_INF;
#pragma unroll
    for (int c = 0; c < NCHUNK; c++) M = fmaxf(M, g_pm[b * NCHUNK + c]);
    if (tid < NCHUNK)
        e_sm[tid] = __expf(g_pm[b * NCHUNK + tid] - M);
    __syncthreads();

    if (tid == 0) {
        float S = 0.f;
#pragma unroll
        for (int c = 0; c < NCHUNK; c++) S = fmaf(g_ps[b * NCHUNK + c], e_sm[c], S);
        Sinv_sm = 1.f / S;
    }
    __syncthreads();
    const float Sinv = Sinv_sm;

#pragma unroll
    for (int r = 0; r < 2; r++) {
        const int d = tid + 256 * r;
        float acc = 0.f;
#pragma unroll
        for (int c = 0; c < NCHUNK; c++)
            acc = fmaf(g_pctx[((size_t)b * NCHUNK + c) * D + d], e_sm[c], acc);
        g_ctx[b * D + d] = acc * Sinv;
    }
}

// ---------------- K3b: out = tanh(ctx@Wv^T + bv + q@Wq^T + bq) ----------------
// grid = (B, 32), block = 256 (8 warps). Each warp computes 2 outputs.
__global__ void __launch_bounds__(256) k3b_out(
    const float* __restrict__ W_query,
    const float* __restrict__ b_query,
    const float* __restrict__ W_value,
    const float* __restrict__ b_value,
    float* __restrict__ out)
{
    const int b    = blockIdx.x;
    const int warp = threadIdx.x >> 5;
    const int lane = threadIdx.x & 31;
    const int d0   = blockIdx.y * 16 + warp * 2;

    const float4* c4 = reinterpret_cast<const float4*>(g_ctx + (size_t)b * D);
    const float4* q4 = reinterpret_cast<const float4*>(g_q   + (size_t)b * D);
    float4 cx[4], qx[4];
#pragma unroll
    for (int k = 0; k < 4; k++) { cx[k] = c4[lane + 32 * k]; qx[k] = q4[lane + 32 * k]; }

    float acc[2] = {0.f, 0.f};
#pragma unroll
    for (int i = 0; i < 2; i++) {
        const float4* wv = reinterpret_cast<const float4*>(W_value + (size_t)(d0 + i) * D);
        const float4* wq = reinterpret_cast<const float4*>(W_query + (size_t)(d0 + i) * D);
#pragma unroll
        for (int k = 0; k < 4; k++) {
            float4 a = wv[lane + 32 * k];
            float4 g = wq[lane + 32 * k];
            acc[i] = fmaf(a.x, cx[k].x, acc[i]); acc[i] = fmaf(a.y, cx[k].y, acc[i]);
            acc[i] = fmaf(a.z, cx[k].z, acc[i]); acc[i] = fmaf(a.w, cx[k].w, acc[i]);
            acc[i] = fmaf(g.x, qx[k].x, acc[i]); acc[i] = fmaf(g.y, qx[k].y, acc[i]);
            acc[i] = fmaf(g.z, qx[k].z, acc[i]); acc[i] = fmaf(g.w, qx[k].w, acc[i]);
        }
    }
#pragma unroll
    for (int o = 16; o > 0; o >>= 1) {
        acc[0] += __shfl_xor_sync(0xffffffffu, acc[0], o);
        acc[1] += __shfl_xor_sync(0xffffffffu, acc[1], o);
    }
    if (lane < 2)
        out[b * D + d0 + lane] = tanhf(acc[lane] + b_value[d0 + lane] + b_query[d0 + lane]);
}

// ---------------- launch ----------------
extern "C" void kernel_launch(void* const* d_in, const int* in_sizes, int n_in,
                              void* d_out, int out_size)
{
    const float* query   = (const float*)d_in[0];
    const float* value   = (const float*)d_in[1];
    const int*   mask    = (const int*)  d_in[2];
    const float* W_align = (const float*)d_in[3];
    const float* b_align = (const float*)d_in[4];
    const float* W_query = (const float*)d_in[5];
    const float* b_query = (const float*)d_in[6];
    const float* W_value = (const float*)d_in[7];
    const float* b_value = (const float*)d_in[8];
    float* out = (float*)d_out;

    const int B = in_sizes[0] / D;          // 16
    const int L = in_sizes[2] / B;          // 8192

    k1_qproj   <<<dim3(B, 16), 256>>>(query, W_align, b_align);
    k2_attn    <<<B * NCHUNK, 256>>>(value, mask, L);
    k3a_combine<<<B, 256>>>();
    k3b_out    <<<dim3(B, 32), 256>>>(W_query, b_query, W_value, b_value, out);
}